// round 4
// baseline (speedup 1.0000x reference)
#include <cuda_runtime.h>
#include <math.h>

#define BATCH 2048
#define LEN   4096
#define NT    256
#define W     16
#define GUARD 32
#define ASZ   (GUARD + LEN + GUARD)   // 4160 floats per signal

__device__ float4   g_rowbuf[BATCH];
__device__ unsigned g_count;

// ---------------- warp reductions ----------------
__device__ __forceinline__ double wredD(double v) {
    #pragma unroll
    for (int o = 16; o; o >>= 1) v += __shfl_down_sync(0xffffffffu, v, o);
    return v;
}
__device__ __forceinline__ int wredI(int v) {
    #pragma unroll
    for (int o = 16; o; o >>= 1) v += __shfl_down_sync(0xffffffffu, v, o);
    return v;
}

// ---------------- one signal pass: d10 mask + d20 count (+fused p2p) ----------
// Thread owns elements [s, s+16) of the guarded smem array. Halo prefix/suffix
// maxes come from neighbor lanes via shfl; lanes 0/31 fall back to smem.
template<bool P2P>
__device__ __forceinline__ void passSignal(
    const float* __restrict__ arr,     // guarded base: element i at arr[GUARD+i]
    int s, int lane,
    unsigned& mask, int& cnt20,
    const float* __restrict__ xarr, unsigned maskx, float& pp)
{
    const float* A = arr + GUARD + s;  // A[j] = element s+j (guards cover j<0, j>=16 edges)

    // reload own block: 4x LDS.128
    float c[W];
    {
        const float4* A4 = (const float4*)A;
        #pragma unroll
        for (int k = 0; k < 4; ++k) {
            float4 q = A4[k];
            c[4*k+0] = q.x; c[4*k+1] = q.y; c[4*k+2] = q.z; c[4*k+3] = q.w;
        }
    }

    // own prefix/suffix maxes
    float Pown[W], Sown[W];
    Pown[0] = c[0];
    #pragma unroll
    for (int k = 1; k < W; ++k) Pown[k] = fmaxf(Pown[k-1], c[k]);
    Sown[W-1] = c[W-1];
    #pragma unroll
    for (int k = W-2; k >= 0; --k) Sown[k] = fmaxf(c[k], Sown[k+1]);

    // halo maxes from neighbor lanes:
    // SP[k] = suffix max of prev block from pos 7+k  (k=0..8) = max(arr[s-9+k .. s-1])
    // PN[k] = prefix max of next block up to pos k   (k=0..8) = max(arr[s+16 .. s+16+k])
    float SP[9], PN[9];
    #pragma unroll
    for (int k = 0; k < 9; ++k) SP[k] = __shfl_up_sync(0xffffffffu, Sown[7+k], 1);
    #pragma unroll
    for (int k = 0; k < 9; ++k) PN[k] = __shfl_down_sync(0xffffffffu, Pown[k], 1);
    float leftV  = __shfl_up_sync(0xffffffffu, c[W-1], 1);
    float rightV = __shfl_down_sync(0xffffffffu, c[0], 1);
    if (lane == 0) {      // prev block lives in another warp (or is the guard)
        SP[8] = A[-1];
        #pragma unroll
        for (int k = 7; k >= 0; --k) SP[k] = fmaxf(A[k-9], SP[k+1]);
        leftV = A[-1];
    }
    if (lane == 31) {     // next block in another warp (or the guard)
        PN[0] = A[W];
        #pragma unroll
        for (int k = 1; k < 9; ++k) PN[k] = fmaxf(PN[k-1], A[W+k]);
        rightV = A[W];
    }
    const float Mfull = Pown[W-1];

    mask = 0u; cnt20 = 0;
    #pragma unroll
    for (int j = 0; j < W; ++j) {
        const float v = c[j];
        const float L = (j == 0)     ? leftV  : c[j-1];
        const float R = (j == W-1)   ? rightV : c[j+1];
        float pooled;   // max over [s+j-9, s+j+9], endpoints within +/-1 block
        if (j <= 6)      pooled = fmaxf(SP[j], Pown[j+9]);
        else if (j <= 8) pooled = fmaxf(fmaxf(SP[j], Mfull), PN[j-7]);
        else             pooled = fmaxf(Sown[j-9], PN[j-7]);
        const int i = s + j;
        const bool ok = (i > 0) & (i < LEN-1) & (v > L) & (v > R);
        const bool pk = ok && (v >= pooled);
        float pky = 0.f;
        if (pk) {
            mask |= (1u << j);
            pky = v;
            // d20 peaks are a subset of d10 peaks: sparse brute check of the
            // extra +/-[10,19] ranges (guards are -inf)
            float lo = A[j-19], hi = A[j+10];
            #pragma unroll
            for (int t = 1; t < 10; ++t) {
                lo = fmaxf(lo, A[j-19+t]);
                hi = fmaxf(hi, A[j+10+t]);
            }
            cnt20 += (v >= lo) && (v >= hi);
        }
        if (P2P) {
            const float pkx = ((maskx >> j) & 1u) ? xarr[GUARD + i] : 0.f;
            const float d = pkx - pky;
            pp += d * d;
        }
    }
}

// ---------------- main kernel ----------------
__global__ void __launch_bounds__(NT, 3)
loss_kernel(const float* __restrict__ xg, const float* __restrict__ yg,
            float* __restrict__ out) {
    __shared__ __align__(16) float xs[ASZ];
    __shared__ __align__(16) float ys[ASZ];
    __shared__ double redd[8 * 5];
    __shared__ int    redi[8 * 2];
    __shared__ int    s_isLast;

    const int tid  = threadIdx.x;
    const int lane = tid & 31;
    const int wid  = tid >> 5;
    const int row  = blockIdx.x;

    // -inf guards
    if (tid < 64) {
        const int idx = (tid < 32) ? tid : (GUARD + LEN + tid - 32);
        xs[idx] = -INFINITY;
        ys[idx] = -INFINITY;
    }

    // Phase 1: block-ordered load (each thread its own 64B chunk, warp-contiguous),
    // elementwise partials in fp32, stage both signals into smem.
    const float4* x4 = (const float4*)(xg + (size_t)row * LEN);
    const float4* y4 = (const float4*)(yg + (size_t)row * LEN);
    float4* xs4 = (float4*)(xs + GUARD);
    float4* ys4 = (float4*)(ys + GUARD);
    float fsd = 0.f, fdt = 0.f, fnx = 0.f, fny = 0.f;
    #pragma unroll
    for (int k = 0; k < 4; ++k) {
        const int j = 4 * tid + k;
        float4 a = x4[j], b = y4[j];
        xs4[j] = a; ys4[j] = b;
        float d0 = a.x - b.x, d1 = a.y - b.y, d2 = a.z - b.z, d3 = a.w - b.w;
        fsd += d0*d0 + d1*d1 + d2*d2 + d3*d3;
        fdt += a.x*b.x + a.y*b.y + a.z*b.z + a.w*b.w;
        fnx += a.x*a.x + a.y*a.y + a.z*a.z + a.w*a.w;
        fny += b.x*b.x + b.y*b.y + b.z*b.z + b.w*b.w;
    }
    __syncthreads();                                   // B1: rows resident

    // Phase 2: x pass then y pass (y pass fuses p2p against x mask)
    const int s = tid * W;
    unsigned mx, my;
    int cx, cy;
    float fpp = 0.f;
    passSignal<false>(xs, s, lane, mx, cx, ys, 0u, fpp);
    passSignal<true >(ys, s, lane, my, cy, xs, mx, fpp);

    // Phase 3: combined block reduction (5 doubles + 2 ints)
    double vals[5] = {(double)fsd, (double)fdt, (double)fnx, (double)fny, (double)fpp};
    #pragma unroll
    for (int k = 0; k < 5; ++k) vals[k] = wredD(vals[k]);
    cx = wredI(cx);
    cy = wredI(cy);
    if (lane == 0) {
        #pragma unroll
        for (int k = 0; k < 5; ++k) redd[wid * 5 + k] = vals[k];
        redi[wid * 2 + 0] = cx;
        redi[wid * 2 + 1] = cy;
    }
    __syncthreads();                                   // B2

    if (tid == 0) {
        double sd = 0, dt = 0, nx = 0, ny = 0, pp = 0;
        int tcx = 0, tcy = 0;
        #pragma unroll
        for (int w = 0; w < NT / 32; ++w) {
            sd += redd[w * 5 + 0]; dt += redd[w * 5 + 1];
            nx += redd[w * 5 + 2]; ny += redd[w * 5 + 3];
            pp += redd[w * 5 + 4];
            tcx += redi[w * 2 + 0]; tcy += redi[w * 2 + 1];
        }
        const double mse_i = sd / (double)LEN;
        const double p2p_i = pp / (double)LEN;
        const double cosv  = dt / (sqrt(nx) * sqrt(ny));
        const double custom = (tcx != tcy) ? mse_i : 0.5 * p2p_i;  // ALPHA=1, BETA=0.5
        float4 r;
        r.x = (float)sd; r.y = (float)cosv; r.z = (float)pp; r.w = (float)custom;
        g_rowbuf[row] = r;
        __threadfence();
        s_isLast = (atomicAdd(&g_count, 1u) == BATCH - 1);
    }
    __syncthreads();                                   // B3

    // Phase 4: last block performs the deterministic final reduction
    if (s_isLast) {
        double s0 = 0, s1 = 0, s2 = 0, s3 = 0;
        for (int r = tid; r < BATCH; r += NT) {
            float4 p = g_rowbuf[r];
            s0 += (double)p.x; s1 += (double)p.y;
            s2 += (double)p.z; s3 += (double)p.w;
        }
        s0 = wredD(s0); s1 = wredD(s1); s2 = wredD(s2); s3 = wredD(s3);
        if (lane == 0) {
            redd[wid * 4 + 0] = s0; redd[wid * 4 + 1] = s1;
            redd[wid * 4 + 2] = s2; redd[wid * 4 + 3] = s3;
        }
        __syncthreads();
        if (tid == 0) {
            double t0 = 0, t1 = 0, t2 = 0, t3 = 0;
            #pragma unroll
            for (int w = 0; w < NT / 32; ++w) {
                t0 += redd[w * 4 + 0]; t1 += redd[w * 4 + 1];
                t2 += redd[w * 4 + 2]; t3 += redd[w * 4 + 3];
            }
            const double mse = t0 / ((double)BATCH * (double)LEN);
            out[0] = (float)(mse + t3);               // total_loss
            out[1] = (float)(t1 / (double)BATCH);     // cosine_similarity
            out[2] = (float)(t2 / (double)LEN);       // p2p_loss
            out[3] = (float)mse;                      // mse_loss
            g_count = 0;                              // reset for next replay
        }
    }
}

extern "C" void kernel_launch(void* const* d_in, const int* in_sizes, int n_in,
                              void* d_out, int out_size) {
    const float* x = (const float*)d_in[0];   // in_signal  [2048, 4096] f32
    const float* y = (const float*)d_in[1];   // ref_signal [2048, 4096] f32
    float* out = (float*)d_out;
    loss_kernel<<<BATCH, NT>>>(x, y, out);
}

// round 5
// speedup vs baseline: 1.2082x; 1.2082x over previous
#include <cuda_runtime.h>
#include <math.h>

#define BATCH 2048
#define LEN   4096
#define NT    256
#define W     19
#define NBLK  218              // 218*19 = 4142 >= 20+4096+19
#define PRE   32               // front guard (-inf), covers reads down to p=-10
#define ASZ   4208             // PRE + 4142 + tail guard, 16B-aligned
// padded coordinate p: signal i lives at p = 20+i, smem idx = p + PRE = 52+i
#define DIDX  52               // smem index of i=0
#define PMIN  21               // first interior p (i=1)
#define PMAX  4114             // last interior p (i=LEN-2)

__device__ float4   g_rowbuf[BATCH];
__device__ unsigned g_count;

// ---------------- warp reductions ----------------
__device__ __forceinline__ double wredD(double v) {
    #pragma unroll
    for (int o = 16; o; o >>= 1) v += __shfl_down_sync(0xffffffffu, v, o);
    return v;
}
__device__ __forceinline__ int wredI(int v) {
    #pragma unroll
    for (int o = 16; o; o >>= 1) v += __shfl_down_sync(0xffffffffu, v, o);
    return v;
}

// ---------------- register-resident van Herk block (trimmed live set) -------
// Thread owns padded block [s, s+19). d10 peak mask + d20 count from its own
// 39-value neighborhood; P2P=true fuses the p2p accumulation vs the x mask.
// Live floats: c[19] + Sl[10] + Pr[9] + Pp10[10] + Sf10[10] = 58.
template<bool P2P>
__device__ __forceinline__ void processBlock(const float* __restrict__ A, int s,
                                             unsigned& mask, int& cnt20,
                                             const float* __restrict__ X,
                                             unsigned maskx, float& pp) {
    const float* B = A + PRE + s;    // B[j] = value at p = s+j

    float c[W];
    #pragma unroll
    for (int j = 0; j < W; ++j) c[j] = B[j];

    // left-halo suffix maxes: Sl[k] = max(B[k-10 .. -1]), k=1..9; Sl[9]=B[-1]
    float Sl[10];
    Sl[9] = B[-1];
    #pragma unroll
    for (int k = 8; k >= 1; --k) Sl[k] = fmaxf(B[k - 10], Sl[k + 1]);

    // right-halo prefix maxes: Pr[k] = max(B[19 .. 19+k]), k=0..8
    float Pr[9];
    Pr[0] = B[W];
    #pragma unroll
    for (int k = 1; k < 9; ++k) Pr[k] = fmaxf(Pr[k - 1], B[W + k]);

    // Pp10[t] = prefix max c[0..t+9]   (t=0..9)  -> used as Pp for j=t<=9
    float Pp10[10];
    {
        float m = c[0];
        #pragma unroll
        for (int k = 1; k < 9; ++k) m = fmaxf(m, c[k]);
        #pragma unroll
        for (int t = 0; t < 10; ++t) { m = fmaxf(m, c[t + 9]); Pp10[t] = m; }
    }
    // Sf10[t] = suffix max c[t..18]    (t=0..9)  -> used as Sp for j=t+9>=9
    float Sf10[10];
    {
        float m = c[W - 1];
        #pragma unroll
        for (int k = W - 2; k >= 10; --k) m = fmaxf(m, c[k]);
        #pragma unroll
        for (int t = 9; t >= 0; --t) { m = fmaxf(m, c[t]); Sf10[t] = m; }
    }

    mask = 0u; cnt20 = 0;
    #pragma unroll
    for (int j = 0; j < W; ++j) {
        const int p = s + j;
        const float v = c[j];
        // pooled19 = max over [p-9, p+9]
        const float Sp = (j >= 9) ? Sf10[j - 9] : Sl[j + 1];
        const float Pp = (j <= 9) ? Pp10[j] : Pr[j - 10];
        const float left  = (j == 0)     ? Sl[9] : c[j - 1];
        const float right = (j == W - 1) ? Pr[0] : c[j + 1];
        const bool ok = (p >= PMIN) & (p <= PMAX) & (v > left) & (v > right);
        const bool pk = ok && (v >= fmaxf(Sp, Pp));
        float pky = 0.f;
        if (pk) {
            mask |= (1u << j);
            pky = v;
            // d20: also require v >= max over [p-19,p-10] and [p+10,p+19]
            float lo = B[j - 19], hi = B[j + 10];
            #pragma unroll
            for (int t = 1; t < 10; ++t) {
                lo = fmaxf(lo, B[j - 19 + t]);
                hi = fmaxf(hi, B[j + 10 + t]);
            }
            cnt20 += (v >= lo) && (v >= hi);
        }
        if (P2P) {
            const float pkx = ((maskx >> j) & 1u) ? X[PRE + s + j] : 0.f;
            const float d = pkx - pky;
            pp += d * d;
        }
    }
}

// ---------------- main kernel ----------------
__global__ void __launch_bounds__(NT, 2)
loss_kernel(const float* __restrict__ xg, const float* __restrict__ yg,
            float* __restrict__ out) {
    __shared__ __align__(16) float xs[ASZ];
    __shared__ __align__(16) float ys[ASZ];
    __shared__ double redd[8 * 5];
    __shared__ int    redi[8 * 2];
    __shared__ int    s_isLast;

    const int tid  = threadIdx.x;
    const int lane = tid & 31;
    const int wid  = tid >> 5;
    const int row  = blockIdx.x;

    // -inf guards: idx [0,52) and [4148, 4208)
    {
        int i = tid;                           // 112 slots, one shot at NT=256
        if (i < 52 + (ASZ - 4148)) {
            int idx = (i < 52) ? i : 4148 + (i - 52);
            xs[idx] = -INFINITY;
            ys[idx] = -INFINITY;
        }
    }

    // Phase 1: coalesced load + fp32 elementwise partials
    const float4* x4 = (const float4*)(xg + (size_t)row * LEN);
    const float4* y4 = (const float4*)(yg + (size_t)row * LEN);
    float4* xs4 = (float4*)(xs + DIDX);
    float4* ys4 = (float4*)(ys + DIDX);
    float fsd = 0.f, fdt = 0.f, fnx = 0.f, fny = 0.f;
    #pragma unroll
    for (int j = tid; j < LEN / 4; j += NT) {
        float4 a = x4[j], b = y4[j];
        xs4[j] = a; ys4[j] = b;
        float d0 = a.x - b.x, d1 = a.y - b.y, d2 = a.z - b.z, d3 = a.w - b.w;
        fsd += d0*d0 + d1*d1 + d2*d2 + d3*d3;
        fdt += a.x*b.x + a.y*b.y + a.z*b.z + a.w*b.w;
        fnx += a.x*a.x + a.y*a.y + a.z*a.z + a.w*a.w;
        fny += b.x*b.x + b.y*b.y + b.z*b.z + b.w*b.w;
    }
    __syncthreads();                                   // B1: rows resident

    // Phase 2: per-thread block processing, x then y (registers only)
    int cx = 0, cy = 0;
    float fpp = 0.f;
    if (tid < NBLK) {
        const int s = tid * W;
        unsigned mx, my;
        int c20;
        processBlock<false>(xs, s, mx, c20, ys, 0u, fpp);
        cx = c20;
        processBlock<true>(ys, s, my, c20, xs, mx, fpp);
        cy = c20;
    }

    // Phase 3: combined block reduction (5 doubles + 2 ints)
    double vals[5] = {(double)fsd, (double)fdt, (double)fnx, (double)fny, (double)fpp};
    #pragma unroll
    for (int k = 0; k < 5; ++k) vals[k] = wredD(vals[k]);
    cx = wredI(cx);
    cy = wredI(cy);
    if (lane == 0) {
        #pragma unroll
        for (int k = 0; k < 5; ++k) redd[wid * 5 + k] = vals[k];
        redi[wid * 2 + 0] = cx;
        redi[wid * 2 + 1] = cy;
    }
    __syncthreads();                                   // B2

    if (tid == 0) {
        double sd = 0, dt = 0, nx = 0, ny = 0, pp = 0;
        int tcx = 0, tcy = 0;
        #pragma unroll
        for (int w = 0; w < NT / 32; ++w) {
            sd += redd[w * 5 + 0]; dt += redd[w * 5 + 1];
            nx += redd[w * 5 + 2]; ny += redd[w * 5 + 3];
            pp += redd[w * 5 + 4];
            tcx += redi[w * 2 + 0]; tcy += redi[w * 2 + 1];
        }
        const double mse_i = sd / (double)LEN;
        const double p2p_i = pp / (double)LEN;
        const double cosv  = dt / (sqrt(nx) * sqrt(ny));
        const double custom = (tcx != tcy) ? mse_i : 0.5 * p2p_i;  // ALPHA=1, BETA=0.5
        float4 r;
        r.x = (float)sd; r.y = (float)cosv; r.z = (float)pp; r.w = (float)custom;
        g_rowbuf[row] = r;
        __threadfence();
        s_isLast = (atomicAdd(&g_count, 1u) == BATCH - 1);
    }
    __syncthreads();                                   // B3

    // Phase 4: last block performs the deterministic final reduction
    if (s_isLast) {
        double s0 = 0, s1 = 0, s2 = 0, s3 = 0;
        for (int r = tid; r < BATCH; r += NT) {
            float4 p = g_rowbuf[r];
            s0 += (double)p.x; s1 += (double)p.y;
            s2 += (double)p.z; s3 += (double)p.w;
        }
        s0 = wredD(s0); s1 = wredD(s1); s2 = wredD(s2); s3 = wredD(s3);
        if (lane == 0) {
            redd[wid * 4 + 0] = s0; redd[wid * 4 + 1] = s1;
            redd[wid * 4 + 2] = s2; redd[wid * 4 + 3] = s3;
        }
        __syncthreads();
        if (tid == 0) {
            double t0 = 0, t1 = 0, t2 = 0, t3 = 0;
            #pragma unroll
            for (int w = 0; w < NT / 32; ++w) {
                t0 += redd[w * 4 + 0]; t1 += redd[w * 4 + 1];
                t2 += redd[w * 4 + 2]; t3 += redd[w * 4 + 3];
            }
            const double mse = t0 / ((double)BATCH * (double)LEN);
            out[0] = (float)(mse + t3);               // total_loss
            out[1] = (float)(t1 / (double)BATCH);     // cosine_similarity
            out[2] = (float)(t2 / (double)LEN);       // p2p_loss
            out[3] = (float)mse;                      // mse_loss
            g_count = 0;                              // reset for next replay
        }
    }
}

extern "C" void kernel_launch(void* const* d_in, const int* in_sizes, int n_in,
                              void* d_out, int out_size) {
    const float* x = (const float*)d_in[0];   // in_signal  [2048, 4096] f32
    const float* y = (const float*)d_in[1];   // ref_signal [2048, 4096] f32
    float* out = (float*)d_out;
    loss_kernel<<<BATCH, NT>>>(x, y, out);
}

// round 6
// speedup vs baseline: 1.4154x; 1.1715x over previous
#include <cuda_runtime.h>
#include <math.h>

#define BATCH 2048
#define LEN   4096
#define NT    256
#define W     19
#define NBLK  218              // 218*19 = 4142 >= 20+4096+19
#define PRE   32               // front guard (-inf), covers reads down to p=-19
#define ASZ   4208             // PRE + 4142 + tail guard, 16B-aligned
// padded coordinate p: signal i lives at p = 20+i, smem idx = p + PRE = 52+i
#define DIDX  52               // smem index of i=0
#define PMIN  21               // first interior p (i=1)
#define PMAX  4114             // last interior p (i=LEN-2)

__device__ float4   g_rowbuf[BATCH];
__device__ unsigned g_count;

// ---------------- warp reductions ----------------
__device__ __forceinline__ double wredD(double v) {
    #pragma unroll
    for (int o = 16; o; o >>= 1) v += __shfl_down_sync(0xffffffffu, v, o);
    return v;
}
__device__ __forceinline__ int wredI(int v) {
    #pragma unroll
    for (int o = 16; o; o >>= 1) v += __shfl_down_sync(0xffffffffu, v, o);
    return v;
}

// ---------------- register-resident van Herk block (fused pooled array) -----
// Thread owns padded block [s, s+19). Computes the d10 peak mask and d20 count
// from its 39-value neighborhood. P2P=true: sparse p2p accumulation over the
// union of both masks (bit-identical to the dense masked-difference sum).
// Peak live floats: c[19] + pooled[19] + ~10 transient.
template<bool P2P>
__device__ __forceinline__ void processBlock(const float* __restrict__ A, int s,
                                             unsigned& mask, int& cnt20,
                                             const float* __restrict__ X,
                                             unsigned maskx, float& pp) {
    const float* B = A + PRE + s;    // B[j] = value at p = s+j

    float c[W];
    #pragma unroll
    for (int j = 0; j < W; ++j) c[j] = B[j];

    float pooled[W];                 // pooled[j] = max over p in [s+j-9, s+j+9]

    // ---- left side: j = 0..8 -> max( B[j-9..-1], c[0..j+9] ); j=9 -> Mfull
    {
        float Sl[10];                // Sl[k] = max(B[k-10 .. -1]), k=1..9
        Sl[9] = B[-1];
        #pragma unroll
        for (int k = 8; k >= 1; --k) Sl[k] = fmaxf(B[k - 10], Sl[k + 1]);
        float m = c[0];
        #pragma unroll
        for (int k = 1; k < 9; ++k) m = fmaxf(m, c[k]);
        #pragma unroll
        for (int t = 0; t <= 8; ++t) {
            m = fmaxf(m, c[t + 9]);               // m = max(c[0 .. t+9])
            pooled[t] = fmaxf(m, Sl[t + 1]);
        }
        pooled[9] = fmaxf(m, c[18]);              // Mfull = max(c[0..18])
    }
    // ---- right side: j = 10..18 -> max( c[j-9..18], B[19..j+9] )
    {
        float Pr[9];                 // Pr[k] = max(B[19 .. 19+k]), k=0..8
        Pr[0] = B[W];
        #pragma unroll
        for (int k = 1; k < 9; ++k) Pr[k] = fmaxf(Pr[k - 1], B[W + k]);
        float m = c[18];
        #pragma unroll
        for (int k = 17; k >= 10; --k) m = fmaxf(m, c[k]);   // m = max(c[10..18])
        #pragma unroll
        for (int t = 9; t >= 1; --t) {
            m = fmaxf(m, c[t]);                   // m = max(c[t .. 18])
            pooled[t + 9] = fmaxf(m, Pr[t - 1]);
        }
    }

    mask = 0u; cnt20 = 0;
    #pragma unroll
    for (int j = 0; j < W; ++j) {
        const int p = s + j;
        const float v = c[j];
        const float left  = (j == 0)     ? B[-1] : c[j - 1];
        const float right = (j == W - 1) ? B[W]  : c[j + 1];
        const bool ok = (p >= PMIN) & (p <= PMAX) & (v > left) & (v > right);
        const bool pk = ok && (v >= pooled[j]);
        if (pk) {
            mask |= (1u << j);
            // d20: also require v >= max over [p-19,p-10] and [p+10,p+19]
            float lo = B[j - 19], hi = B[j + 10];
            #pragma unroll
            for (int t = 1; t < 10; ++t) {
                lo = fmaxf(lo, B[j - 19 + t]);
                hi = fmaxf(hi, B[j + 10 + t]);
            }
            cnt20 += (v >= lo) && (v >= hi);
        }
    }

    if (P2P) {  // sparse: nonzero terms only where either signal has a peak
        unsigned un = maskx | mask;
        while (un) {
            const int j = __ffs(un) - 1;
            un &= un - 1;
            const float pkx = ((maskx >> j) & 1u) ? X[PRE + s + j] : 0.f;
            const float pky = ((mask  >> j) & 1u) ? A[PRE + s + j] : 0.f;
            const float d = pkx - pky;
            pp += d * d;
        }
    }
}

// ---------------- main kernel ----------------
__global__ void __launch_bounds__(NT, 3)
loss_kernel(const float* __restrict__ xg, const float* __restrict__ yg,
            float* __restrict__ out) {
    __shared__ __align__(16) float xs[ASZ];
    __shared__ __align__(16) float ys[ASZ];
    __shared__ double redd[8 * 5];
    __shared__ int    redi[8 * 2];
    __shared__ int    s_isLast;

    const int tid  = threadIdx.x;
    const int lane = tid & 31;
    const int wid  = tid >> 5;
    const int row  = blockIdx.x;

    // -inf guards: idx [0,52) and [4148, 4208)
    {
        int i = tid;                           // 112 slots, one shot at NT=256
        if (i < 52 + (ASZ - 4148)) {
            int idx = (i < 52) ? i : 4148 + (i - 52);
            xs[idx] = -INFINITY;
            ys[idx] = -INFINITY;
        }
    }

    // Phase 1: coalesced load + fp32 elementwise partials
    const float4* x4 = (const float4*)(xg + (size_t)row * LEN);
    const float4* y4 = (const float4*)(yg + (size_t)row * LEN);
    float4* xs4 = (float4*)(xs + DIDX);
    float4* ys4 = (float4*)(ys + DIDX);
    float fsd = 0.f, fdt = 0.f, fnx = 0.f, fny = 0.f;
    #pragma unroll
    for (int j = tid; j < LEN / 4; j += NT) {
        float4 a = x4[j], b = y4[j];
        xs4[j] = a; ys4[j] = b;
        float d0 = a.x - b.x, d1 = a.y - b.y, d2 = a.z - b.z, d3 = a.w - b.w;
        fsd += d0*d0 + d1*d1 + d2*d2 + d3*d3;
        fdt += a.x*b.x + a.y*b.y + a.z*b.z + a.w*b.w;
        fnx += a.x*a.x + a.y*a.y + a.z*a.z + a.w*a.w;
        fny += b.x*b.x + b.y*b.y + b.z*b.z + b.w*b.w;
    }
    __syncthreads();                                   // B1: rows resident

    // Phase 2: per-thread block processing, x then y (registers only)
    int cx = 0, cy = 0;
    float fpp = 0.f;
    if (tid < NBLK) {
        const int s = tid * W;
        unsigned mx, my;
        int c20;
        processBlock<false>(xs, s, mx, c20, ys, 0u, fpp);
        cx = c20;
        processBlock<true>(ys, s, my, c20, xs, mx, fpp);
        cy = c20;
    }

    // Phase 3: combined block reduction (5 doubles + 2 ints)
    double vals[5] = {(double)fsd, (double)fdt, (double)fnx, (double)fny, (double)fpp};
    #pragma unroll
    for (int k = 0; k < 5; ++k) vals[k] = wredD(vals[k]);
    cx = wredI(cx);
    cy = wredI(cy);
    if (lane == 0) {
        #pragma unroll
        for (int k = 0; k < 5; ++k) redd[wid * 5 + k] = vals[k];
        redi[wid * 2 + 0] = cx;
        redi[wid * 2 + 1] = cy;
    }
    __syncthreads();                                   // B2

    if (tid == 0) {
        double sd = 0, dt = 0, nx = 0, ny = 0, pp = 0;
        int tcx = 0, tcy = 0;
        #pragma unroll
        for (int w = 0; w < NT / 32; ++w) {
            sd += redd[w * 5 + 0]; dt += redd[w * 5 + 1];
            nx += redd[w * 5 + 2]; ny += redd[w * 5 + 3];
            pp += redd[w * 5 + 4];
            tcx += redi[w * 2 + 0]; tcy += redi[w * 2 + 1];
        }
        const double mse_i = sd / (double)LEN;
        const double p2p_i = pp / (double)LEN;
        const double cosv  = dt / (sqrt(nx) * sqrt(ny));
        const double custom = (tcx != tcy) ? mse_i : 0.5 * p2p_i;  // ALPHA=1, BETA=0.5
        float4 r;
        r.x = (float)sd; r.y = (float)cosv; r.z = (float)pp; r.w = (float)custom;
        g_rowbuf[row] = r;
        __threadfence();
        s_isLast = (atomicAdd(&g_count, 1u) == BATCH - 1);
    }
    __syncthreads();                                   // B3

    // Phase 4: last block performs the deterministic final reduction
    if (s_isLast) {
        double s0 = 0, s1 = 0, s2 = 0, s3 = 0;
        for (int r = tid; r < BATCH; r += NT) {
            float4 p = g_rowbuf[r];
            s0 += (double)p.x; s1 += (double)p.y;
            s2 += (double)p.z; s3 += (double)p.w;
        }
        s0 = wredD(s0); s1 = wredD(s1); s2 = wredD(s2); s3 = wredD(s3);
        if (lane == 0) {
            redd[wid * 4 + 0] = s0; redd[wid * 4 + 1] = s1;
            redd[wid * 4 + 2] = s2; redd[wid * 4 + 3] = s3;
        }
        __syncthreads();
        if (tid == 0) {
            double t0 = 0, t1 = 0, t2 = 0, t3 = 0;
            #pragma unroll
            for (int w = 0; w < NT / 32; ++w) {
                t0 += redd[w * 4 + 0]; t1 += redd[w * 4 + 1];
                t2 += redd[w * 4 + 2]; t3 += redd[w * 4 + 3];
            }
            const double mse = t0 / ((double)BATCH * (double)LEN);
            out[0] = (float)(mse + t3);               // total_loss
            out[1] = (float)(t1 / (double)BATCH);     // cosine_similarity
            out[2] = (float)(t2 / (double)LEN);       // p2p_loss
            out[3] = (float)mse;                      // mse_loss
            g_count = 0;                              // reset for next replay
        }
    }
}

extern "C" void kernel_launch(void* const* d_in, const int* in_sizes, int n_in,
                              void* d_out, int out_size) {
    const float* x = (const float*)d_in[0];   // in_signal  [2048, 4096] f32
    const float* y = (const float*)d_in[1];   // ref_signal [2048, 4096] f32
    float* out = (float*)d_out;
    loss_kernel<<<BATCH, NT>>>(x, y, out);
}

// round 7
// speedup vs baseline: 1.4219x; 1.0046x over previous
#include <cuda_runtime.h>
#include <math.h>

#define BATCH 2048
#define LEN   4096
#define NT    256
#define W     19
#define NBLK  218              // 218*19 = 4142 >= 20+4096+19
#define PRE   32               // front guard (-inf), covers reads down to p=-19
#define ASZ   4208             // PRE + 4142 + tail guard, 16B-aligned
// padded coordinate p: signal i lives at p = 20+i, smem idx = p + PRE = 52+i
#define DIDX  52               // smem index of i=0
#define PMIN  21               // first interior p (i=1)
#define PMAX  4114             // last interior p (i=LEN-2)

__device__ float4   g_rowbuf[BATCH];
__device__ unsigned g_count;

// ---------------- warp reductions ----------------
__device__ __forceinline__ double wredD(double v) {
    #pragma unroll
    for (int o = 16; o; o >>= 1) v += __shfl_down_sync(0xffffffffu, v, o);
    return v;
}
__device__ __forceinline__ int wredI(int v) {
    #pragma unroll
    for (int o = 16; o; o >>= 1) v += __shfl_down_sync(0xffffffffu, v, o);
    return v;
}

// sparse d20 membership test at a known d10 peak (guards are -inf)
__device__ __forceinline__ int d20At(const float* __restrict__ B, int j, float v) {
    float lo = B[j - 19], hi = B[j + 10];
    #pragma unroll
    for (int t = 1; t < 10; ++t) {
        lo = fmaxf(lo, B[j - 19 + t]);
        hi = fmaxf(hi, B[j + 10 + t]);
    }
    return (v >= lo) && (v >= hi);
}

// ---------------- register-resident van Herk block (fully fused) ------------
// Thread owns padded block [s, s+19). Peak tests are fused into the pooled-max
// build loops so no pooled[] array is materialized (reg diet for 4 CTAs/SM).
// P2P=true: sparse p2p accumulation over the union of both masks afterwards.
template<bool P2P>
__device__ __forceinline__ void processBlock(const float* __restrict__ A, int s,
                                             unsigned& mask, int& cnt20,
                                             const float* __restrict__ X,
                                             unsigned maskx, float& pp) {
    const float* B = A + PRE + s;    // B[j] = value at p = s+j

    float c[W];
    #pragma unroll
    for (int j = 0; j < W; ++j) c[j] = B[j];

    mask = 0u; cnt20 = 0;

    // ---- left: j = 0..8, pooled = max( Sl[j+1], c[0..j+9] ); then j = 9
    {
        float Sl[10];                // Sl[k] = max(B[k-10 .. -1]), k=1..9
        Sl[9] = B[-1];
        #pragma unroll
        for (int k = 8; k >= 1; --k) Sl[k] = fmaxf(B[k - 10], Sl[k + 1]);

        float m = c[0];
        #pragma unroll
        for (int k = 1; k < 9; ++k) m = fmaxf(m, c[k]);     // m = max(c[0..8])
        #pragma unroll
        for (int j = 0; j <= 8; ++j) {
            m = fmaxf(m, c[j + 9]);                         // m = max(c[0..j+9])
            const float v = c[j];
            const float left  = (j == 0) ? Sl[9] : c[j - 1];
            const int p = s + j;
            const bool ok = (p >= PMIN) & (p <= PMAX) & (v > left) & (v > c[j + 1]);
            if (ok && v >= fmaxf(m, Sl[j + 1])) {
                mask |= (1u << j);
                cnt20 += d20At(B, j, v);
            }
        }
        // j = 9: pooled = max(c[0..18])
        const float v = c[9];
        const bool ok = (v > c[8]) & (v > c[10]);           // p interior always
        if (ok && v >= fmaxf(m, c[18])) {
            mask |= (1u << 9);
            cnt20 += d20At(B, 9, v);
        }
    }
    // ---- right: j = 18..10, pooled = max( c[j-9..18], Pr[j-10] )
    {
        float Pr[9];                 // Pr[k] = max(B[19 .. 19+k]), k=0..8
        Pr[0] = B[W];
        #pragma unroll
        for (int k = 1; k < 9; ++k) Pr[k] = fmaxf(Pr[k - 1], B[W + k]);

        float m = c[18];
        #pragma unroll
        for (int k = 17; k >= 10; --k) m = fmaxf(m, c[k]);  // m = max(c[10..18])
        #pragma unroll
        for (int t = 9; t >= 1; --t) {
            const int j = t + 9;                            // 18..10
            m = fmaxf(m, c[t]);                             // m = max(c[t..18])
            const float v = c[j];
            const float right = (j == W - 1) ? Pr[0] : c[j + 1];
            const int p = s + j;
            const bool ok = (p >= PMIN) & (p <= PMAX) & (v > c[j - 1]) & (v > right);
            if (ok && v >= fmaxf(m, Pr[t - 1])) {
                mask |= (1u << j);
                cnt20 += d20At(B, j, v);
            }
        }
    }

    if (P2P) {  // sparse: nonzero terms only where either signal has a peak
        unsigned un = maskx | mask;
        while (un) {
            const int j = __ffs(un) - 1;
            un &= un - 1;
            const float pkx = ((maskx >> j) & 1u) ? X[PRE + s + j] : 0.f;
            const float pky = ((mask  >> j) & 1u) ? B[j] : 0.f;
            const float d = pkx - pky;
            pp += d * d;
        }
    }
}

// ---------------- main kernel ----------------
__global__ void __launch_bounds__(NT, 4)
loss_kernel(const float* __restrict__ xg, const float* __restrict__ yg,
            float* __restrict__ out) {
    __shared__ __align__(16) float xs[ASZ];
    __shared__ __align__(16) float ys[ASZ];
    __shared__ double redd[8 * 5];
    __shared__ int    redi[8 * 2];
    __shared__ int    s_isLast;

    const int tid  = threadIdx.x;
    const int lane = tid & 31;
    const int wid  = tid >> 5;
    const int row  = blockIdx.x;

    // -inf guards: idx [0,52) and [4148, 4208)
    {
        int i = tid;                           // 112 slots, one shot at NT=256
        if (i < 52 + (ASZ - 4148)) {
            int idx = (i < 52) ? i : 4148 + (i - 52);
            xs[idx] = -INFINITY;
            ys[idx] = -INFINITY;
        }
    }

    // Phase 1: coalesced load + fp32 elementwise partials
    const float4* x4 = (const float4*)(xg + (size_t)row * LEN);
    const float4* y4 = (const float4*)(yg + (size_t)row * LEN);
    float4* xs4 = (float4*)(xs + DIDX);
    float4* ys4 = (float4*)(ys + DIDX);
    float fsd = 0.f, fdt = 0.f, fnx = 0.f, fny = 0.f;
    #pragma unroll
    for (int j = tid; j < LEN / 4; j += NT) {
        float4 a = x4[j], b = y4[j];
        xs4[j] = a; ys4[j] = b;
        float d0 = a.x - b.x, d1 = a.y - b.y, d2 = a.z - b.z, d3 = a.w - b.w;
        fsd += d0*d0 + d1*d1 + d2*d2 + d3*d3;
        fdt += a.x*b.x + a.y*b.y + a.z*b.z + a.w*b.w;
        fnx += a.x*a.x + a.y*a.y + a.z*a.z + a.w*a.w;
        fny += b.x*b.x + b.y*b.y + b.z*b.z + b.w*b.w;
    }
    __syncthreads();                                   // B1: rows resident

    // Phase 2: per-thread block processing, x then y (registers only)
    int cx = 0, cy = 0;
    float fpp = 0.f;
    if (tid < NBLK) {
        const int s = tid * W;
        unsigned mx, my;
        int c20;
        processBlock<false>(xs, s, mx, c20, ys, 0u, fpp);
        cx = c20;
        processBlock<true>(ys, s, my, c20, xs, mx, fpp);
        cy = c20;
    }

    // Phase 3: combined block reduction (5 doubles + 2 ints)
    double vals[5] = {(double)fsd, (double)fdt, (double)fnx, (double)fny, (double)fpp};
    #pragma unroll
    for (int k = 0; k < 5; ++k) vals[k] = wredD(vals[k]);
    cx = wredI(cx);
    cy = wredI(cy);
    if (lane == 0) {
        #pragma unroll
        for (int k = 0; k < 5; ++k) redd[wid * 5 + k] = vals[k];
        redi[wid * 2 + 0] = cx;
        redi[wid * 2 + 1] = cy;
    }
    __syncthreads();                                   // B2

    if (tid == 0) {
        double sd = 0, dt = 0, nx = 0, ny = 0, pp = 0;
        int tcx = 0, tcy = 0;
        #pragma unroll
        for (int w = 0; w < NT / 32; ++w) {
            sd += redd[w * 5 + 0]; dt += redd[w * 5 + 1];
            nx += redd[w * 5 + 2]; ny += redd[w * 5 + 3];
            pp += redd[w * 5 + 4];
            tcx += redi[w * 2 + 0]; tcy += redi[w * 2 + 1];
        }
        const double mse_i = sd / (double)LEN;
        const double p2p_i = pp / (double)LEN;
        const double cosv  = dt / (sqrt(nx) * sqrt(ny));
        const double custom = (tcx != tcy) ? mse_i : 0.5 * p2p_i;  // ALPHA=1, BETA=0.5
        float4 r;
        r.x = (float)sd; r.y = (float)cosv; r.z = (float)pp; r.w = (float)custom;
        g_rowbuf[row] = r;
        __threadfence();
        s_isLast = (atomicAdd(&g_count, 1u) == BATCH - 1);
    }
    __syncthreads();                                   // B3

    // Phase 4: last block performs the deterministic final reduction
    if (s_isLast) {
        double s0 = 0, s1 = 0, s2 = 0, s3 = 0;
        for (int r = tid; r < BATCH; r += NT) {
            float4 p = g_rowbuf[r];
            s0 += (double)p.x; s1 += (double)p.y;
            s2 += (double)p.z; s3 += (double)p.w;
        }
        s0 = wredD(s0); s1 = wredD(s1); s2 = wredD(s2); s3 = wredD(s3);
        if (lane == 0) {
            redd[wid * 4 + 0] = s0; redd[wid * 4 + 1] = s1;
            redd[wid * 4 + 2] = s2; redd[wid * 4 + 3] = s3;
        }
        __syncthreads();
        if (tid == 0) {
            double t0 = 0, t1 = 0, t2 = 0, t3 = 0;
            #pragma unroll
            for (int w = 0; w < NT / 32; ++w) {
                t0 += redd[w * 4 + 0]; t1 += redd[w * 4 + 1];
                t2 += redd[w * 4 + 2]; t3 += redd[w * 4 + 3];
            }
            const double mse = t0 / ((double)BATCH * (double)LEN);
            out[0] = (float)(mse + t3);               // total_loss
            out[1] = (float)(t1 / (double)BATCH);     // cosine_similarity
            out[2] = (float)(t2 / (double)LEN);       // p2p_loss
            out[3] = (float)mse;                      // mse_loss
            g_count = 0;                              // reset for next replay
        }
    }
}

extern "C" void kernel_launch(void* const* d_in, const int* in_sizes, int n_in,
                              void* d_out, int out_size) {
    const float* x = (const float*)d_in[0];   // in_signal  [2048, 4096] f32
    const float* y = (const float*)d_in[1];   // ref_signal [2048, 4096] f32
    float* out = (float*)d_out;
    loss_kernel<<<BATCH, NT>>>(x, y, out);
}

// round 8
// speedup vs baseline: 1.4553x; 1.0235x over previous
#include <cuda_runtime.h>
#include <math.h>

#define BATCH 2048
#define LEN   4096
#define NT    256
#define W     19
#define NBLK  218              // 218*19 = 4142 >= 20+4096+19
#define PRE   32               // front guard (-inf), covers reads down to p=-19
#define ASZ   4208             // PRE + 4142 + tail guard, 16B-aligned
// padded coordinate p: signal i lives at p = 20+i, smem idx = p + PRE = 52+i
#define DIDX  52               // smem index of i=0

__device__ float4   g_rowbuf[BATCH];
__device__ unsigned g_count;

// ---------------- warp reductions ----------------
__device__ __forceinline__ double wredD(double v) {
    #pragma unroll
    for (int o = 16; o; o >>= 1) v += __shfl_down_sync(0xffffffffu, v, o);
    return v;
}
__device__ __forceinline__ int wredI(int v) {
    #pragma unroll
    for (int o = 16; o; o >>= 1) v += __shfl_down_sync(0xffffffffu, v, o);
    return v;
}

// sparse d20 membership test at a known d10 peak (guards are -inf)
__device__ __forceinline__ int d20At(const float* __restrict__ B, int j, float v) {
    float lo = B[j - 19], hi = B[j + 10];
    #pragma unroll
    for (int t = 1; t < 10; ++t) {
        lo = fmaxf(lo, B[j - 19 + t]);
        hi = fmaxf(hi, B[j + 10 + t]);
    }
    return (v >= lo) && (v >= hi);
}

// ---------------- register-resident van Herk block (fully fused) ------------
// Thread owns padded block [s, s+19). Peak tests fused into the pooled-max
// build loops. No interior-range checks: the -inf guards exclude all pad
// positions; the only false positives (i=0 at p=20, i=LEN-1 at p=4115) are
// corrected after the loops at their owning (thread, j) slots.
template<bool P2P>
__device__ __forceinline__ void processBlock(const float* __restrict__ A, int s,
                                             unsigned& mask, int& cnt20,
                                             const float* __restrict__ X,
                                             unsigned maskx, float& pp) {
    const float* B = A + PRE + s;    // B[j] = value at p = s+j

    float c[W];
    #pragma unroll
    for (int j = 0; j < W; ++j) c[j] = B[j];

    mask = 0u; cnt20 = 0;

    // ---- left: j = 0..8, pooled = max( Sl[j+1], c[0..j+9] ); then j = 9
    {
        float Sl[10];                // Sl[k] = max(B[k-10 .. -1]), k=1..9
        Sl[9] = B[-1];
        #pragma unroll
        for (int k = 8; k >= 1; --k) Sl[k] = fmaxf(B[k - 10], Sl[k + 1]);

        float m = c[0];
        #pragma unroll
        for (int k = 1; k < 9; ++k) m = fmaxf(m, c[k]);     // m = max(c[0..8])
        #pragma unroll
        for (int j = 0; j <= 8; ++j) {
            m = fmaxf(m, c[j + 9]);                         // m = max(c[0..j+9])
            const float v = c[j];
            const float left = (j == 0) ? Sl[9] : c[j - 1];
            const float nb = fmaxf(left, c[j + 1]);
            if (v > nb && v >= fmaxf(m, Sl[j + 1])) {
                mask |= (1u << j);
                cnt20 += d20At(B, j, v);
            }
        }
        // j = 9: pooled = max(c[0..18])
        const float v = c[9];
        const float nb = fmaxf(c[8], c[10]);
        if (v > nb && v >= fmaxf(m, c[18])) {
            mask |= (1u << 9);
            cnt20 += d20At(B, 9, v);
        }
    }
    // ---- right: j = 18..10, pooled = max( c[j-9..18], Pr[j-10] )
    {
        float Pr[9];                 // Pr[k] = max(B[19 .. 19+k]), k=0..8
        Pr[0] = B[W];
        #pragma unroll
        for (int k = 1; k < 9; ++k) Pr[k] = fmaxf(Pr[k - 1], B[W + k]);

        float m = c[18];
        #pragma unroll
        for (int k = 17; k >= 10; --k) m = fmaxf(m, c[k]);  // m = max(c[10..18])
        #pragma unroll
        for (int t = 9; t >= 1; --t) {
            const int j = t + 9;                            // 18..10
            m = fmaxf(m, c[t]);                             // m = max(c[t..18])
            const float v = c[j];
            const float right = (j == W - 1) ? Pr[0] : c[j + 1];
            const float nb = fmaxf(c[j - 1], right);
            if (v > nb && v >= fmaxf(m, Pr[t - 1])) {
                mask |= (1u << j);
                cnt20 += d20At(B, j, v);
            }
        }
    }

    // edge corrections: i=0 lives at (s=19, j=1); i=LEN-1 at (s=4104, j=11)
    if (s == 19 && (mask & (1u << 1))) {
        mask &= ~(1u << 1);
        cnt20 -= d20At(B, 1, B[1]);
    }
    if (s == 4104 && (mask & (1u << 11))) {
        mask &= ~(1u << 11);
        cnt20 -= d20At(B, 11, B[11]);
    }

    if (P2P) {  // sparse: nonzero terms only where either signal has a peak
        unsigned un = maskx | mask;
        while (un) {
            const int j = __ffs(un) - 1;
            un &= un - 1;
            const float pkx = ((maskx >> j) & 1u) ? X[PRE + s + j] : 0.f;
            const float pky = ((mask  >> j) & 1u) ? B[j] : 0.f;
            const float d = pkx - pky;
            pp += d * d;
        }
    }
}

// ---------------- main kernel ----------------
__global__ void __launch_bounds__(NT, 4)
loss_kernel(const float* __restrict__ xg, const float* __restrict__ yg,
            float* __restrict__ out) {
    __shared__ __align__(16) float xs[ASZ];
    __shared__ __align__(16) float ys[ASZ];
    __shared__ double redd[8 * 4];
    __shared__ int    redi[8 * 2];
    __shared__ int    s_isLast;

    const int tid  = threadIdx.x;
    const int lane = tid & 31;
    const int wid  = tid >> 5;
    const int row  = blockIdx.x;

    // -inf guards: idx [0,52) and [4148, 4208)
    {
        int i = tid;                           // 112 slots, one shot at NT=256
        if (i < 52 + (ASZ - 4148)) {
            int idx = (i < 52) ? i : 4148 + (i - 52);
            xs[idx] = -INFINITY;
            ys[idx] = -INFINITY;
        }
    }

    // Phase 1: coalesced load + fp32 elementwise partials (dot + norms only;
    // sum of squared diffs recovered as nx - 2*dt + ny in fp64 at combine)
    const float4* x4 = (const float4*)(xg + (size_t)row * LEN);
    const float4* y4 = (const float4*)(yg + (size_t)row * LEN);
    float4* xs4 = (float4*)(xs + DIDX);
    float4* ys4 = (float4*)(ys + DIDX);
    float fdt = 0.f, fnx = 0.f, fny = 0.f;
    #pragma unroll
    for (int j = tid; j < LEN / 4; j += NT) {
        float4 a = x4[j], b = y4[j];
        xs4[j] = a; ys4[j] = b;
        fdt += a.x*b.x + a.y*b.y + a.z*b.z + a.w*b.w;
        fnx += a.x*a.x + a.y*a.y + a.z*a.z + a.w*a.w;
        fny += b.x*b.x + b.y*b.y + b.z*b.z + b.w*b.w;
    }
    __syncthreads();                                   // B1: rows resident

    // Phase 2: per-thread block processing, x then y (registers only)
    int cx = 0, cy = 0;
    float fpp = 0.f;
    if (tid < NBLK) {
        const int s = tid * W;
        unsigned mx, my;
        int c20;
        processBlock<false>(xs, s, mx, c20, ys, 0u, fpp);
        cx = c20;
        processBlock<true>(ys, s, my, c20, xs, mx, fpp);
        cy = c20;
    }

    // Phase 3: combined block reduction (4 doubles + 2 ints)
    double vals[4] = {(double)fdt, (double)fnx, (double)fny, (double)fpp};
    #pragma unroll
    for (int k = 0; k < 4; ++k) vals[k] = wredD(vals[k]);
    cx = wredI(cx);
    cy = wredI(cy);
    if (lane == 0) {
        #pragma unroll
        for (int k = 0; k < 4; ++k) redd[wid * 4 + k] = vals[k];
        redi[wid * 2 + 0] = cx;
        redi[wid * 2 + 1] = cy;
    }
    __syncthreads();                                   // B2

    if (tid == 0) {
        double dt = 0, nx = 0, ny = 0, pp = 0;
        int tcx = 0, tcy = 0;
        #pragma unroll
        for (int w = 0; w < NT / 32; ++w) {
            dt += redd[w * 4 + 0]; nx += redd[w * 4 + 1];
            ny += redd[w * 4 + 2]; pp += redd[w * 4 + 3];
            tcx += redi[w * 2 + 0]; tcy += redi[w * 2 + 1];
        }
        const double sd = nx - 2.0 * dt + ny;          // sum (a-b)^2
        const double mse_i = sd / (double)LEN;
        const double p2p_i = pp / (double)LEN;
        const double cosv  = dt / (sqrt(nx) * sqrt(ny));
        const double custom = (tcx != tcy) ? mse_i : 0.5 * p2p_i;  // ALPHA=1, BETA=0.5
        float4 r;
        r.x = (float)sd; r.y = (float)cosv; r.z = (float)pp; r.w = (float)custom;
        g_rowbuf[row] = r;
        __threadfence();
        s_isLast = (atomicAdd(&g_count, 1u) == BATCH - 1);
    }
    __syncthreads();                                   // B3

    // Phase 4: last block performs the deterministic final reduction
    if (s_isLast) {
        double s0 = 0, s1 = 0, s2 = 0, s3 = 0;
        for (int r = tid; r < BATCH; r += NT) {
            float4 p = g_rowbuf[r];
            s0 += (double)p.x; s1 += (double)p.y;
            s2 += (double)p.z; s3 += (double)p.w;
        }
        s0 = wredD(s0); s1 = wredD(s1); s2 = wredD(s2); s3 = wredD(s3);
        if (lane == 0) {
            redd[wid * 4 + 0] = s0; redd[wid * 4 + 1] = s1;
            redd[wid * 4 + 2] = s2; redd[wid * 4 + 3] = s3;
        }
        __syncthreads();
        if (tid == 0) {
            double t0 = 0, t1 = 0, t2 = 0, t3 = 0;
            #pragma unroll
            for (int w = 0; w < NT / 32; ++w) {
                t0 += redd[w * 4 + 0]; t1 += redd[w * 4 + 1];
                t2 += redd[w * 4 + 2]; t3 += redd[w * 4 + 3];
            }
            const double mse = t0 / ((double)BATCH * (double)LEN);
            out[0] = (float)(mse + t3);               // total_loss
            out[1] = (float)(t1 / (double)BATCH);     // cosine_similarity
            out[2] = (float)(t2 / (double)LEN);       // p2p_loss
            out[3] = (float)mse;                      // mse_loss
            g_count = 0;                              // reset for next replay
        }
    }
}

extern "C" void kernel_launch(void* const* d_in, const int* in_sizes, int n_in,
                              void* d_out, int out_size) {
    const float* x = (const float*)d_in[0];   // in_signal  [2048, 4096] f32
    const float* y = (const float*)d_in[1];   // ref_signal [2048, 4096] f32
    float* out = (float*)d_out;
    loss_kernel<<<BATCH, NT>>>(x, y, out);
}

// round 9
// speedup vs baseline: 1.7052x; 1.1717x over previous
#include <cuda_runtime.h>
#include <math.h>

#define BATCH 2048
#define LEN   4096
#define NT    256
#define W     19
#define NBLK  218              // 218*19 = 4142 >= 20+4096+19
#define PRE   32               // front guard (-inf), covers reads down to p=-19
#define ASZ   4208             // PRE + 4142 + tail guard, 16B-aligned
// padded coordinate p: signal i lives at p = 20+i, smem idx = p + PRE = 52+i
#define DIDX  52               // smem index of i=0

__device__ float4   g_rowbuf[BATCH];
__device__ unsigned g_count;

// ---------------- warp reductions ----------------
__device__ __forceinline__ double wredD(double v) {
    #pragma unroll
    for (int o = 16; o; o >>= 1) v += __shfl_down_sync(0xffffffffu, v, o);
    return v;
}
__device__ __forceinline__ int wredI(int v) {
    #pragma unroll
    for (int o = 16; o; o >>= 1) v += __shfl_down_sync(0xffffffffu, v, o);
    return v;
}

// ---------------- register-resident van Herk block, dense d10+d20 -----------
// Thread owns padded block [s, s+19). Full halo chains give both the d10
// pooled window and the d20 window test with no divergent loads:
//   Sl[k] = max(B[k-19 .. -1])   (prev 19 positions, suffix maxes)
//   Pr[k] = max(B[19 .. 19+k])   (next 19 positions, prefix maxes)
// d20 window [p-19, p+19] = prev[j..18] + own block + next[0..j], so
//   peak20 = peak10 && v>=Sl[j] && v>=Pr[j] && v>=Mfull.
template<bool P2P>
__device__ __forceinline__ void processBlock(const float* __restrict__ A, int s,
                                             unsigned& mask, int& cnt20,
                                             const float* __restrict__ X,
                                             unsigned maskx, float& pp) {
    const float* B = A + PRE + s;    // B[j] = value at p = s+j

    float c[W];
    #pragma unroll
    for (int j = 0; j < W; ++j) c[j] = B[j];

    float Sl[W];                     // Sl[k] = max(B[k-19 .. -1])
    Sl[18] = B[-1];
    #pragma unroll
    for (int k = 17; k >= 0; --k) Sl[k] = fmaxf(B[k - 19], Sl[k + 1]);

    float Pr[W];                     // Pr[k] = max(B[19 .. 19+k])
    Pr[0] = B[W];
    #pragma unroll
    for (int k = 1; k < W; ++k) Pr[k] = fmaxf(Pr[k - 1], B[W + k]);

    float Mfull = c[0];              // max of own block
    #pragma unroll
    for (int k = 1; k < W; ++k) Mfull = fmaxf(Mfull, c[k]);

    unsigned m10 = 0u, m20 = 0u;

    // ---- left: j = 0..8, pooled19 = max( Sl[j+10], c[0..j+9] )
    {
        float m = c[0];
        #pragma unroll
        for (int k = 1; k < 9; ++k) m = fmaxf(m, c[k]);     // m = max(c[0..8])
        #pragma unroll
        for (int j = 0; j <= 8; ++j) {
            m = fmaxf(m, c[j + 9]);                         // m = max(c[0..j+9])
            const float v = c[j];
            const float left = (j == 0) ? Sl[18] : c[j - 1];
            const float nb = fmaxf(left, c[j + 1]);
            if (v > nb && v >= fmaxf(m, Sl[j + 10])) {
                m10 |= (1u << j);
                if (v >= Sl[j] && v >= Pr[j] && v >= Mfull) m20 |= (1u << j);
            }
        }
    }
    // ---- center: j = 9, pooled19 = Mfull
    {
        const float v = c[9];
        const float nb = fmaxf(c[8], c[10]);
        if (v > nb && v >= Mfull) {
            m10 |= (1u << 9);
            if (v >= Sl[9] && v >= Pr[9]) m20 |= (1u << 9);
        }
    }
    // ---- right: j = 18..10, pooled19 = max( c[j-9..18], Pr[j-10] )
    {
        float m = c[18];
        #pragma unroll
        for (int k = 17; k >= 10; --k) m = fmaxf(m, c[k]);  // m = max(c[10..18])
        #pragma unroll
        for (int t = 9; t >= 1; --t) {
            const int j = t + 9;                            // 18..10
            m = fmaxf(m, c[t]);                             // m = max(c[t..18])
            const float v = c[j];
            const float right = (j == W - 1) ? Pr[0] : c[j + 1];
            const float nb = fmaxf(c[j - 1], right);
            if (v > nb && v >= fmaxf(m, Pr[t - 1])) {
                m10 |= (1u << j);
                if (v >= Sl[j] && v >= Pr[j] && v >= Mfull) m20 |= (1u << j);
            }
        }
    }

    // edge corrections: i=0 lives at (s=19, j=1); i=LEN-1 at (s=4104, j=11)
    if (s == 19)   { m10 &= ~(1u << 1);  m20 &= ~(1u << 1);  }
    if (s == 4104) { m10 &= ~(1u << 11); m20 &= ~(1u << 11); }

    mask = m10;
    cnt20 = __popc(m20);

    if (P2P) {  // sparse: nonzero terms only where either signal has a peak
        unsigned un = maskx | mask;
        while (un) {
            const int j = __ffs(un) - 1;
            un &= un - 1;
            const float pkx = ((maskx >> j) & 1u) ? X[PRE + s + j] : 0.f;
            const float pky = ((mask  >> j) & 1u) ? B[j] : 0.f;
            const float d = pkx - pky;
            pp += d * d;
        }
    }
}

// ---------------- main kernel ----------------
__global__ void __launch_bounds__(NT, 3)
loss_kernel(const float* __restrict__ xg, const float* __restrict__ yg,
            float* __restrict__ out) {
    __shared__ __align__(16) float xs[ASZ];
    __shared__ __align__(16) float ys[ASZ];
    __shared__ double redd[8 * 4];
    __shared__ int    redi[8 * 2];
    __shared__ int    s_isLast;

    const int tid  = threadIdx.x;
    const int lane = tid & 31;
    const int wid  = tid >> 5;
    const int row  = blockIdx.x;

    // -inf guards: idx [0,52) and [4148, 4208)
    {
        int i = tid;                           // 112 slots, one shot at NT=256
        if (i < 52 + (ASZ - 4148)) {
            int idx = (i < 52) ? i : 4148 + (i - 52);
            xs[idx] = -INFINITY;
            ys[idx] = -INFINITY;
        }
    }

    // Phase 1: coalesced load + fp32 elementwise partials (dot + norms only;
    // sum of squared diffs recovered as nx - 2*dt + ny in fp64 at combine)
    const float4* x4 = (const float4*)(xg + (size_t)row * LEN);
    const float4* y4 = (const float4*)(yg + (size_t)row * LEN);
    float4* xs4 = (float4*)(xs + DIDX);
    float4* ys4 = (float4*)(ys + DIDX);
    float fdt = 0.f, fnx = 0.f, fny = 0.f;
    #pragma unroll
    for (int j = tid; j < LEN / 4; j += NT) {
        float4 a = x4[j], b = y4[j];
        xs4[j] = a; ys4[j] = b;
        fdt += a.x*b.x + a.y*b.y + a.z*b.z + a.w*b.w;
        fnx += a.x*a.x + a.y*a.y + a.z*a.z + a.w*a.w;
        fny += b.x*b.x + b.y*b.y + b.z*b.z + b.w*b.w;
    }
    __syncthreads();                                   // B1: rows resident

    // Phase 2: per-thread block processing, x then y (registers only)
    int cx = 0, cy = 0;
    float fpp = 0.f;
    if (tid < NBLK) {
        const int s = tid * W;
        unsigned mx, my;
        int c20;
        processBlock<false>(xs, s, mx, c20, ys, 0u, fpp);
        cx = c20;
        processBlock<true>(ys, s, my, c20, xs, mx, fpp);
        cy = c20;
    }

    // Phase 3: combined block reduction (4 doubles + 2 ints)
    double vals[4] = {(double)fdt, (double)fnx, (double)fny, (double)fpp};
    #pragma unroll
    for (int k = 0; k < 4; ++k) vals[k] = wredD(vals[k]);
    cx = wredI(cx);
    cy = wredI(cy);
    if (lane == 0) {
        #pragma unroll
        for (int k = 0; k < 4; ++k) redd[wid * 4 + k] = vals[k];
        redi[wid * 2 + 0] = cx;
        redi[wid * 2 + 1] = cy;
    }
    __syncthreads();                                   // B2

    if (tid == 0) {
        double dt = 0, nx = 0, ny = 0, pp = 0;
        int tcx = 0, tcy = 0;
        #pragma unroll
        for (int w = 0; w < NT / 32; ++w) {
            dt += redd[w * 4 + 0]; nx += redd[w * 4 + 1];
            ny += redd[w * 4 + 2]; pp += redd[w * 4 + 3];
            tcx += redi[w * 2 + 0]; tcy += redi[w * 2 + 1];
        }
        const double sd = nx - 2.0 * dt + ny;          // sum (a-b)^2
        const double mse_i = sd / (double)LEN;
        const double p2p_i = pp / (double)LEN;
        const double cosv  = dt / (sqrt(nx) * sqrt(ny));
        const double custom = (tcx != tcy) ? mse_i : 0.5 * p2p_i;  // ALPHA=1, BETA=0.5
        float4 r;
        r.x = (float)sd; r.y = (float)cosv; r.z = (float)pp; r.w = (float)custom;
        g_rowbuf[row] = r;
        __threadfence();
        s_isLast = (atomicAdd(&g_count, 1u) == BATCH - 1);
    }
    __syncthreads();                                   // B3

    // Phase 4: last block performs the deterministic final reduction
    if (s_isLast) {
        double s0 = 0, s1 = 0, s2 = 0, s3 = 0;
        for (int r = tid; r < BATCH; r += NT) {
            float4 p = g_rowbuf[r];
            s0 += (double)p.x; s1 += (double)p.y;
            s2 += (double)p.z; s3 += (double)p.w;
        }
        s0 = wredD(s0); s1 = wredD(s1); s2 = wredD(s2); s3 = wredD(s3);
        if (lane == 0) {
            redd[wid * 4 + 0] = s0; redd[wid * 4 + 1] = s1;
            redd[wid * 4 + 2] = s2; redd[wid * 4 + 3] = s3;
        }
        __syncthreads();
        if (tid == 0) {
            double t0 = 0, t1 = 0, t2 = 0, t3 = 0;
            #pragma unroll
            for (int w = 0; w < NT / 32; ++w) {
                t0 += redd[w * 4 + 0]; t1 += redd[w * 4 + 1];
                t2 += redd[w * 4 + 2]; t3 += redd[w * 4 + 3];
            }
            const double mse = t0 / ((double)BATCH * (double)LEN);
            out[0] = (float)(mse + t3);               // total_loss
            out[1] = (float)(t1 / (double)BATCH);     // cosine_similarity
            out[2] = (float)(t2 / (double)LEN);       // p2p_loss
            out[3] = (float)mse;                      // mse_loss
            g_count = 0;                              // reset for next replay
        }
    }
}

extern "C" void kernel_launch(void* const* d_in, const int* in_sizes, int n_in,
                              void* d_out, int out_size) {
    const float* x = (const float*)d_in[0];   // in_signal  [2048, 4096] f32
    const float* y = (const float*)d_in[1];   // ref_signal [2048, 4096] f32
    float* out = (float*)d_out;
    loss_kernel<<<BATCH, NT>>>(x, y, out);
}